// round 8
// baseline (speedup 1.0000x reference)
#include <cuda_runtime.h>
#include <math.h>

// x: [B=256, K=1048576]; memory: [E=8, K]
#define BN   256
#define EN   8
#define KN   1048576
#define K4N  (KN / 4)
#define CK   512             // k per chunk (block)
#define CK4  (CK / 4)        // 128
#define NCH  (KN / CK)       // 2048 chunks
#define KS   16              // k-slice per pipeline stage (1 KB per warp-slice)
#define NSL  (CK / KS)       // 32 slices per chunk
#define MSTR 516             // m_s row stride: 516 % 32 == 4 (conflict-free B)
#define XBUF 256             // slice buffer floats per warp (16 rows x 16 cols)
#define NSTG 3               // pipeline stages
#define DSMEM ((8 * MSTR + 8 * NSTG * XBUF) * 4)   // 41088 B

// x_s swizzle: off = row*16 + col, sw = off ^ (((row>>1)&7)<<2).
// A-load banks: b01=tg, b23=k^(g>>1 low), b4=g&1 -> 32 distinct. 16B aligned.
#define XSW(row, col) (((row) * 16 + (col)) ^ ((((row) >> 1) & 7) << 2))

// Scratch (device globals -- no allocation allowed).
// g_dotp layout: [b][j][c], j=0..7 dot partial per expert, j=8 ||x||^2 partial
__device__ float g_dotp[(size_t)BN * 9 * NCH];   // 18.9 MB
__device__ float g_mpart[EN * NCH];
__device__ int   g_experts[BN];

__device__ __forceinline__ float warp_sum(float v) {
    #pragma unroll
    for (int o = 16; o; o >>= 1)
        v += __shfl_xor_sync(0xffffffffu, v, o);
    return v;
}

// tf32 m16n8k8 MMA: D += A(16x8) * B(8x8) (fp32 bits reinterpreted as tf32).
__device__ __forceinline__ void mma_tf32(float acc[4],
                                         float a0, float a1, float a2, float a3,
                                         float b0, float b1) {
    asm volatile(
        "mma.sync.aligned.m16n8k8.row.col.f32.tf32.tf32.f32 "
        "{%0,%1,%2,%3}, {%4,%5,%6,%7}, {%8,%9}, {%0,%1,%2,%3};\n"
        : "+f"(acc[0]), "+f"(acc[1]), "+f"(acc[2]), "+f"(acc[3])
        : "r"(__float_as_uint(a0)), "r"(__float_as_uint(a1)),
          "r"(__float_as_uint(a2)), "r"(__float_as_uint(a3)),
          "r"(__float_as_uint(b0)), "r"(__float_as_uint(b1)));
}

// 16B async copy gmem -> smem, L2-only (streaming x).
__device__ __forceinline__ void cpa16(unsigned dst, const void* src) {
    asm volatile("cp.async.cg.shared.global [%0], [%1], 16;\n"
                 :: "r"(dst), "l"(src));
}

// ---------------------------------------------------------------------------
// Pass 1: tensor-core dot partials + exact fp32 norms.
// Block: 8 warps, 128 b-rows (16 per warp), one k-chunk of 512.
// Per-warp x staging: 1 KB slices, TRIPLE buffered, cp.async committed 2
// slices ahead (wait_group 2) so 2 slices are always in flight per warp ->
// the L1tex/DRAM queue never drains between slice rounds.
// ---------------------------------------------------------------------------
__global__ void __launch_bounds__(256) k_dots(const float* __restrict__ x,
                                              const float* __restrict__ mem)
{
    extern __shared__ float smem_[];
    float* m_s = smem_;                        // 8 * 516 floats
    float* x_s = smem_ + 8 * MSTR;             // 8 warps * 3 * 256 floats

    const int c   = blockIdx.x;                // chunk
    const int bt  = blockIdx.y;                // b tile (0..1), 128 b each
    const int tid = threadIdx.x;
    const int w   = tid >> 5;
    const int l   = tid & 31;
    const int g   = l >> 2;                    // 0..7  (mma groupID)
    const int tg  = l & 3;                     // 0..3
    const int r02 = l >> 2;                    // 0..7  (staging row base)
    const int q2  = l & 3;                     // 0..3  (staging float4 col)

    // ---- stage m chunk: 1024 float4 / 256 threads = 4 each (coalesced) ----
    const float4* m4 = (const float4*)mem;
    #pragma unroll
    for (int i = 0; i < 4; ++i) {
        int slot = tid + 256 * i;              // 0..1023
        int e = slot >> 7;                     // /128
        int qq = slot & 127;
        float4 v = m4[(size_t)e * K4N + (size_t)c * CK4 + qq];
        *(float4*)&m_s[e * MSTR + 4 * qq] = v;
    }
    __syncthreads();

    // ---- ||m_e||^2 chunk partials (bt==0 only; warp w == expert w) ----
    if (bt == 0) {
        float s = 0.f;
        #pragma unroll
        for (int j = 0; j < 4; ++j) {
            float4 f = *(const float4*)&m_s[w * MSTR + 4 * (l + 32 * j)];
            s += f.x * f.x + f.y * f.y + f.z * f.z + f.w * f.w;
        }
        s = warp_sum(s);
        if (l == 0) g_mpart[w * NCH + c] = s;
    }

    // ---- main loop: warp owns rows b0row..b0row+15 ----
    const int b0row = bt * 128 + w * 16;
    // lane stages rows r02 and r02+8, 16B at float4-col q2 of each slice
    const float4* xb0 = (const float4*)x
                      + (size_t)(b0row + r02) * K4N + (size_t)c * CK4 + q2;
    const float4* xb1 = (const float4*)x
                      + (size_t)(b0row + r02 + 8) * K4N + (size_t)c * CK4 + q2;

    float* xw = x_s + w * (NSTG * XBUF);
    const unsigned xs_base = (unsigned)__cvta_generic_to_shared(xw);
    const unsigned d0 = xs_base + (unsigned)(XSW(r02,     4 * q2) * 4);
    const unsigned d1 = xs_base + (unsigned)(XSW(r02 + 8, 4 * q2) * 4);

    float acc[4] = {0.f, 0.f, 0.f, 0.f};
    float n0 = 0.f, n1 = 0.f, n2 = 0.f, n3 = 0.f;

    // precomputed swizzled A-load offsets (col part added per k)
    const int swA_lo = XSW(g,     0) + tg;     // row g base
    const int swA_hi = XSW(g + 8, 0) + tg;     // row g+8 base
    // NOTE: XSW only flips bits 2..4 of the col field; adding tg (0..3, bits
    // 0..1) and k (multiple of 4... k in {0,8} plus +4) must go through XSW.
    // k+tg and k+4+tg have bits overlapping the swizzle mask, so compute
    // full XSW per access instead:
    #define ALD(row_expr, col_expr) xw[(sb) * XBUF + XSW((row_expr), (col_expr))]

    // prologue: slices 0 and 1
    #pragma unroll
    for (int s0 = 0; s0 < 2; ++s0) {
        const unsigned boff = (unsigned)(s0 * XBUF * 4);
        cpa16(d0 + boff, xb0 + (size_t)s0 * 4);
        cpa16(d1 + boff, xb1 + (size_t)s0 * 4);
        asm volatile("cp.async.commit_group;\n" ::: "memory");
    }

    #pragma unroll 1
    for (int s = 0; s < NSL; ++s) {
        if (s + 2 < NSL) {
            // buffer (s+2)%3 was consumed at iter s-1 (trailing syncwarp)
            const unsigned boff = (unsigned)(((s + 2) % 3) * XBUF * 4);
            cpa16(d0 + boff, xb0 + (size_t)(s + 2) * 4);
            cpa16(d1 + boff, xb1 + (size_t)(s + 2) * 4);
            asm volatile("cp.async.commit_group;\n" ::: "memory");
            asm volatile("cp.async.wait_group 2;\n" ::: "memory");
        } else if (s + 1 < NSL) {
            asm volatile("cp.async.wait_group 1;\n" ::: "memory");
        } else {
            asm volatile("cp.async.wait_group 0;\n" ::: "memory");
        }
        __syncwarp();

        const int sb = s % 3;
        const int cbase = s * KS;
        #pragma unroll
        for (int k8 = 0; k8 < KS / 8; ++k8) {
            const int k = k8 * 8;
            float a0 = ALD(g,     k + tg);
            float a1 = ALD(g + 8, k + tg);
            float a2 = ALD(g,     k + 4 + tg);
            float a3 = ALD(g + 8, k + 4 + tg);
            float b0 = m_s[g * MSTR + cbase + k + tg];
            float b1 = m_s[g * MSTR + cbase + k + 4 + tg];

            n0 += a0 * a0;  n1 += a2 * a2;
            n2 += a1 * a1;  n3 += a3 * a3;

            mma_tf32(acc, a0, a1, a2, a3, b0, b1);
        }
        __syncwarp();   // all lanes done reading buffer s%3 before refill
    }
    #undef ALD

    // ---- write dot partials: D[r][e], r = g / g+8, e = 2tg / 2tg+1 ----
    const size_t bl = (size_t)(b0row + g)     * 9 * NCH;
    const size_t bh = (size_t)(b0row + g + 8) * 9 * NCH;
    g_dotp[bl + (size_t)(2 * tg)     * NCH + c] = acc[0];
    g_dotp[bl + (size_t)(2 * tg + 1) * NCH + c] = acc[1];
    g_dotp[bh + (size_t)(2 * tg)     * NCH + c] = acc[2];
    g_dotp[bh + (size_t)(2 * tg + 1) * NCH + c] = acc[3];

    // ---- norms: reduce across the 4 lanes of each g-group ----
    float ng  = n0 + n1;    // row g
    float ng8 = n2 + n3;    // row g+8
    ng  += __shfl_xor_sync(0xffffffffu, ng, 1);
    ng  += __shfl_xor_sync(0xffffffffu, ng, 2);
    ng8 += __shfl_xor_sync(0xffffffffu, ng8, 1);
    ng8 += __shfl_xor_sync(0xffffffffu, ng8, 2);
    if (tg == 0) {
        g_dotp[bl + (size_t)8 * NCH + c] = ng;
        g_dotp[bh + (size_t)8 * NCH + c] = ng8;
    }
}

// ---------------------------------------------------------------------------
// Pass 2: reduce chunk partials, cosine sim, argmax (first-max rule).
// ---------------------------------------------------------------------------
__global__ void __launch_bounds__(256) k_argmax(float* __restrict__ outExp)
{
    const int b   = blockIdx.x;
    const int tid = threadIdx.x;
    const int w   = tid >> 5;
    const int l   = tid & 31;

    __shared__ float sdot[EN];
    __shared__ float smn[EN];
    __shared__ float snx;

    {
        const float* p = g_dotp + (size_t)b * 9 * NCH + (size_t)w * NCH;
        float v = 0.f;
        #pragma unroll
        for (int g = 0; g < NCH / 32; ++g) v += p[g * 32 + l];
        v = warp_sum(v);
        if (l == 0) sdot[w] = v;
    }
    if (w == 0) {
        const float* p = g_dotp + (size_t)b * 9 * NCH + (size_t)8 * NCH;
        float v = 0.f;
        #pragma unroll
        for (int g = 0; g < NCH / 32; ++g) v += p[g * 32 + l];
        v = warp_sum(v);
        if (l == 0) snx = v;
    }
    {
        const float* p = g_mpart + (size_t)w * NCH;
        float v = 0.f;
        #pragma unroll
        for (int g = 0; g < NCH / 32; ++g) v += p[g * 32 + l];
        v = warp_sum(v);
        if (l == 0) smn[w] = v;
    }
    __syncthreads();

    if (tid == 0) {
        float nx = sqrtf(snx);
        float best = -3.4e38f;
        int   bi   = 0;
        #pragma unroll
        for (int e = 0; e < EN; ++e) {
            float denom = fmaxf(nx * sqrtf(smn[e]), 1e-8f);
            float s = sdot[e] / denom;
            if (s > best) { best = s; bi = e; }   // strict > == first-max (jnp.argmax)
        }
        g_experts[b] = bi;
        if (outExp) outExp[b] = (float)bi;
    }
}

// ---------------------------------------------------------------------------
// Pass 3: scatter-mean update with integrated ballot counting-sort prologue
// (every block recomputes the stable order from g_experts; deterministic).
// ---------------------------------------------------------------------------
__global__ void __launch_bounds__(256) k_update(const float* __restrict__ x,
                                                const float* __restrict__ mem,
                                                float* __restrict__ outMem)
{
    __shared__ int   s_order[BN];
    __shared__ int   s_offs[EN + 1];
    __shared__ float s_ka[EN];
    __shared__ float s_kb[EN];
    __shared__ int   wcnt[8][EN];

    const int tid = threadIdx.x;       // tid == b for the sort prologue
    const int w = tid >> 5, l = tid & 31;

    // ---- stable counting sort by expert (ballot ranking) ----
    if (tid < 8 * EN) ((int*)wcnt)[tid] = 0;
    __syncthreads();

    const int e = g_experts[tid];
    unsigned mk = __match_any_sync(0xffffffffu, e);
    int lower = __popc(mk & ((1u << l) - 1u));
    if (lower == 0) wcnt[w][e] = __popc(mk);
    __syncthreads();

    if (tid < EN) {
        int t = 0;
        #pragma unroll
        for (int ww = 0; ww < 8; ++ww) t += wcnt[ww][tid];
        s_offs[tid + 1] = t;
        if (t > 0) { s_ka[tid] = 0.5f; s_kb[tid] = 0.5f / (float)t; }
        else       { s_ka[tid] = 1.0f; s_kb[tid] = 0.0f; }
    }
    __syncthreads();
    if (tid == 0) {
        s_offs[0] = 0;
        #pragma unroll
        for (int i = 0; i < EN; ++i) s_offs[i + 1] += s_offs[i];
    }
    __syncthreads();

    {
        int rank = lower;
        #pragma unroll
        for (int ww = 0; ww < 8; ++ww)
            if (ww < w) rank += wcnt[ww][e];
        s_order[s_offs[e] + rank] = tid;
    }
    __syncthreads();

    // ---- streaming update ----
    const size_t j4 = (size_t)blockIdx.x * 256 + tid;
    const float4* x4 = (const float4*)x;
    const float4* m4 = (const float4*)mem;
    float4*       o4 = (float4*)outMem;

    #pragma unroll 1
    for (int ee = 0; ee < EN; ++ee) {
        float ax = 0.f, ay = 0.f, az = 0.f, aw = 0.f;
        const int lo = s_offs[ee];
        const int hi = s_offs[ee + 1];
        #pragma unroll 4
        for (int i = lo; i < hi; ++i) {
            int b = s_order[i];
            float4 f = x4[(size_t)b * K4N + j4];
            ax += f.x; ay += f.y; az += f.z; aw += f.w;
        }
        const float ka = s_ka[ee];
        const float kb = s_kb[ee];
        float4 mv = m4[(size_t)ee * K4N + j4];
        float4 ov;
        ov.x = ka * mv.x + kb * ax;
        ov.y = ka * mv.y + kb * ay;
        ov.z = ka * mv.z + kb * az;
        ov.w = ka * mv.w + kb * aw;
        o4[(size_t)ee * K4N + j4] = ov;
    }
}

// ---------------------------------------------------------------------------
extern "C" void kernel_launch(void* const* d_in, const int* in_sizes, int n_in,
                              void* d_out, int out_size)
{
    const float* x   = (const float*)d_in[0];
    const float* mem = (const float*)d_in[1];
    float* out = (float*)d_out;

    const long memElems = (long)EN * KN;          // 8388608
    float* outExp = nullptr;
    float* outMem = nullptr;
    if ((long)out_size == memElems + BN) {        // concat: experts then new_memory
        outExp = out;
        outMem = out + BN;
    } else if ((long)out_size == memElems) {      // new_memory only
        outMem = out;
    } else {                                      // experts only (fallback)
        outExp = out;
    }

    cudaFuncSetAttribute(k_dots, cudaFuncAttributeMaxDynamicSharedMemorySize, DSMEM);

    dim3 g1(NCH, 2);
    k_dots<<<g1, 256, DSMEM>>>(x, mem);
    k_argmax<<<BN, 256>>>(outExp);
    if (outMem) k_update<<<K4N / 256, 256>>>(x, mem, outMem);
}

// round 9
// speedup vs baseline: 1.4814x; 1.4814x over previous
#include <cuda_runtime.h>
#include <math.h>

// x: [B=256, K=1048576]; memory: [E=8, K]
#define BN   256
#define EN   8
#define KN   1048576
#define K4N  (KN / 4)
#define CK   512             // chunk size in floats (k per block)
#define CK4  (CK / 4)        // 128
#define NCH  (KN / CK)       // 2048 chunks
#define KS   32              // k-slice staged in smem per warp step
#define NSL  (CK / KS)       // 16 slices per chunk
#define XSTR 36              // x_s row stride (floats): 4g+tg distinct mod 32
#define MSTR 516             // m_s row stride (floats): 516 % 32 == 4
#define XBUF (16 * XSTR)     // one slice buffer (floats) per warp
#define NSTG 3               // x pipeline stages (prefetch depth 2)
#define DSMEM ((8 * MSTR + 8 * NSTG * XBUF) * 4)   // 71808 B dynamic smem

// Scratch (device globals -- no allocation allowed).
// g_dotp layout: [b][j][c], j=0..7 dot partial per expert, j=8 ||x||^2 partial
__device__ float g_dotp[(size_t)BN * 9 * NCH];   // 18.9 MB
__device__ float g_mpart[EN * NCH];
__device__ int   g_experts[BN];

__device__ __forceinline__ float warp_sum(float v) {
    #pragma unroll
    for (int o = 16; o; o >>= 1)
        v += __shfl_xor_sync(0xffffffffu, v, o);
    return v;
}

// tf32 m16n8k8 MMA: D += A(16x8) * B(8x8) (fp32 bits reinterpreted as tf32).
__device__ __forceinline__ void mma_tf32(float acc[4],
                                         float a0, float a1, float a2, float a3,
                                         float b0, float b1) {
    asm volatile(
        "mma.sync.aligned.m16n8k8.row.col.f32.tf32.tf32.f32 "
        "{%0,%1,%2,%3}, {%4,%5,%6,%7}, {%8,%9}, {%0,%1,%2,%3};\n"
        : "+f"(acc[0]), "+f"(acc[1]), "+f"(acc[2]), "+f"(acc[3])
        : "r"(__float_as_uint(a0)), "r"(__float_as_uint(a1)),
          "r"(__float_as_uint(a2)), "r"(__float_as_uint(a3)),
          "r"(__float_as_uint(b0)), "r"(__float_as_uint(b1)));
}

// 16B async copy gmem -> smem, L2-only (streaming x).
__device__ __forceinline__ void cpa16(unsigned dst, const void* src) {
    asm volatile("cp.async.cg.shared.global [%0], [%1], 16;\n"
                 :: "r"(dst), "l"(src));
}

// ---------------------------------------------------------------------------
// Pass 1: tensor-core dot partials + exact fp32 norms.
// Block: 8 warps, 128 b-rows (16 per warp), one k-chunk of 512.
// x staged per-warp via cp.async, TRIPLE buffered with commits TWO slices
// ahead (wait_group 2): while MMA consumes slice s, slices s+1 and s+2 are
// in flight -> the DRAM queue never drains on service jitter.
// Addressing uses padded strides (compile-time constants, no runtime swizzle).
// ---------------------------------------------------------------------------
__global__ void __launch_bounds__(256) k_dots(const float* __restrict__ x,
                                              const float* __restrict__ mem)
{
    extern __shared__ float smem_[];
    float* m_s = smem_;                        // 8 * 516 floats
    float* x_s = smem_ + 8 * MSTR;             // 8 warps * 3 * 16*36 floats

    const int c   = blockIdx.x;                // chunk
    const int bt  = blockIdx.y;                // b tile (0..1), 128 b each
    const int tid = threadIdx.x;
    const int w   = tid >> 5;
    const int l   = tid & 31;
    const int g   = l >> 2;                    // 0..7  (mma groupID)
    const int tg  = l & 3;                     // 0..3
    const int r0  = l >> 3;                    // 0..3  (staging row base)
    const int q   = l & 7;                     // 0..7  (staging quad col)

    // ---- stage m chunk: 1024 float4 / 256 threads = 4 each (coalesced) ----
    const float4* m4 = (const float4*)mem;
    #pragma unroll
    for (int i = 0; i < 4; ++i) {
        int slot = tid + 256 * i;              // 0..1023
        int e = slot >> 7;                     // /128
        int qq = slot & 127;
        float4 v = m4[(size_t)e * K4N + (size_t)c * CK4 + qq];
        *(float4*)&m_s[e * MSTR + 4 * qq] = v;
    }
    __syncthreads();

    // ---- ||m_e||^2 chunk partials (one b-tile only; warp w == expert w) ----
    if (bt == 0) {
        float s = 0.f;
        #pragma unroll
        for (int j = 0; j < 4; ++j) {
            float4 f = *(const float4*)&m_s[w * MSTR + 4 * (l + 32 * j)];
            s += f.x * f.x + f.y * f.y + f.z * f.z + f.w * f.w;
        }
        s = warp_sum(s);
        if (l == 0) g_mpart[w * NCH + c] = s;
    }

    // ---- main loop: warp owns rows b0row..b0row+15 ----
    const int b0row = bt * 128 + w * 16;
    const float4* xb = (const float4*)x
                     + (size_t)(b0row + r0) * K4N + (size_t)c * CK4 + q;

    float* xw_base = x_s + w * (NSTG * XBUF);
    const unsigned xs_t = (unsigned)__cvta_generic_to_shared(xw_base)
                        + (unsigned)((r0 * XSTR + 4 * q) * 4);

    float acc[4] = {0.f, 0.f, 0.f, 0.f};
    float n0 = 0.f, n1 = 0.f, n2 = 0.f, n3 = 0.f;

    // prologue: slices 0 and 1 -> buffers 0 and 1
    #pragma unroll
    for (int s0 = 0; s0 < 2; ++s0) {
        const unsigned boff = (unsigned)(s0 * XBUF * 4);
        #pragma unroll
        for (int i = 0; i < 4; ++i)
            cpa16(xs_t + boff + (unsigned)(i * 4 * XSTR * 4),
                  xb + (size_t)i * 4 * K4N + (size_t)s0 * 8);
        asm volatile("cp.async.commit_group;\n" ::: "memory");
    }

    int sb = 0;                                // consume buffer index
    int wb = 2;                                // write buffer index
    #pragma unroll 1
    for (int s = 0; s < NSL; ++s) {
        if (s + 2 < NSL) {
            // buffer wb's last reader finished at iter s-1 (trailing syncwarp)
            const unsigned nb = (unsigned)(wb * XBUF * 4);
            #pragma unroll
            for (int i = 0; i < 4; ++i)
                cpa16(xs_t + nb + (unsigned)(i * 4 * XSTR * 4),
                      xb + (size_t)i * 4 * K4N + (size_t)(s + 2) * 8);
            asm volatile("cp.async.commit_group;\n" ::: "memory");
            asm volatile("cp.async.wait_group 2;\n" ::: "memory");
        } else if (s + 1 < NSL) {
            asm volatile("cp.async.wait_group 1;\n" ::: "memory");
        } else {
            asm volatile("cp.async.wait_group 0;\n" ::: "memory");
        }
        __syncwarp();

        const float* xw = xw_base + sb * XBUF;
        const int cbase = s * KS;
        #pragma unroll
        for (int k8 = 0; k8 < KS / 8; ++k8) {
            const int k = k8 * 8;
            // A fragments (row-major 16x8): rows g, g+8; cols k+tg, k+4+tg
            float a0 = xw[g       * XSTR + k + tg];
            float a1 = xw[(g + 8) * XSTR + k + tg];
            float a2 = xw[g       * XSTR + k + 4 + tg];
            float a3 = xw[(g + 8) * XSTR + k + 4 + tg];
            // B fragments (col-major 8x8): B[k][n] = m[n][k]; n = g
            float b0 = m_s[g * MSTR + cbase + k + tg];
            float b1 = m_s[g * MSTR + cbase + k + 4 + tg];

            // exact fp32 norms (4 independent chains)
            n0 += a0 * a0;  n1 += a2 * a2;
            n2 += a1 * a1;  n3 += a3 * a3;

            mma_tf32(acc, a0, a1, a2, a3, b0, b1);
        }
        __syncwarp();   // all lanes done reading buffer sb before it refills

        sb = (sb == 2) ? 0 : sb + 1;
        wb = (wb == 2) ? 0 : wb + 1;
    }

    // ---- write dot partials: D[r][e], r = g / g+8, e = 2tg / 2tg+1 ----
    const size_t bl = (size_t)(b0row + g)     * 9 * NCH;
    const size_t bh = (size_t)(b0row + g + 8) * 9 * NCH;
    g_dotp[bl + (size_t)(2 * tg)     * NCH + c] = acc[0];
    g_dotp[bl + (size_t)(2 * tg + 1) * NCH + c] = acc[1];
    g_dotp[bh + (size_t)(2 * tg)     * NCH + c] = acc[2];
    g_dotp[bh + (size_t)(2 * tg + 1) * NCH + c] = acc[3];

    // ---- norms: reduce across the 4 lanes of each g-group ----
    float ng  = n0 + n1;    // row g
    float ng8 = n2 + n3;    // row g+8
    ng  += __shfl_xor_sync(0xffffffffu, ng, 1);
    ng  += __shfl_xor_sync(0xffffffffu, ng, 2);
    ng8 += __shfl_xor_sync(0xffffffffu, ng8, 1);
    ng8 += __shfl_xor_sync(0xffffffffu, ng8, 2);
    if (tg == 0) {
        g_dotp[bl + (size_t)8 * NCH + c] = ng;
        g_dotp[bh + (size_t)8 * NCH + c] = ng8;
    }
}

// ---------------------------------------------------------------------------
// Pass 2: reduce chunk partials, cosine sim, argmax (first-max rule).
// ---------------------------------------------------------------------------
__global__ void __launch_bounds__(256) k_argmax(float* __restrict__ outExp)
{
    const int b   = blockIdx.x;
    const int tid = threadIdx.x;
    const int w   = tid >> 5;
    const int l   = tid & 31;

    __shared__ float sdot[EN];
    __shared__ float smn[EN];
    __shared__ float snx;

    {
        const float* p = g_dotp + (size_t)b * 9 * NCH + (size_t)w * NCH;
        float v = 0.f;
        #pragma unroll
        for (int g = 0; g < NCH / 32; ++g) v += p[g * 32 + l];
        v = warp_sum(v);
        if (l == 0) sdot[w] = v;
    }
    if (w == 0) {
        const float* p = g_dotp + (size_t)b * 9 * NCH + (size_t)8 * NCH;
        float v = 0.f;
        #pragma unroll
        for (int g = 0; g < NCH / 32; ++g) v += p[g * 32 + l];
        v = warp_sum(v);
        if (l == 0) snx = v;
    }
    {
        const float* p = g_mpart + (size_t)w * NCH;
        float v = 0.f;
        #pragma unroll
        for (int g = 0; g < NCH / 32; ++g) v += p[g * 32 + l];
        v = warp_sum(v);
        if (l == 0) smn[w] = v;
    }
    __syncthreads();

    if (tid == 0) {
        float nx = sqrtf(snx);
        float best = -3.4e38f;
        int   bi   = 0;
        #pragma unroll
        for (int e = 0; e < EN; ++e) {
            float denom = fmaxf(nx * sqrtf(smn[e]), 1e-8f);
            float s = sdot[e] / denom;
            if (s > best) { best = s; bi = e; }   // strict > == first-max (jnp.argmax)
        }
        g_experts[b] = bi;
        if (outExp) outExp[b] = (float)bi;
    }
}

// ---------------------------------------------------------------------------
// Pass 3: scatter-mean update with integrated ballot counting-sort prologue
// (every block recomputes the stable order from g_experts; deterministic).
// ---------------------------------------------------------------------------
__global__ void __launch_bounds__(256) k_update(const float* __restrict__ x,
                                                const float* __restrict__ mem,
                                                float* __restrict__ outMem)
{
    __shared__ int   s_order[BN];
    __shared__ int   s_offs[EN + 1];
    __shared__ float s_ka[EN];
    __shared__ float s_kb[EN];
    __shared__ int   wcnt[8][EN];

    const int tid = threadIdx.x;       // tid == b for the sort prologue
    const int w = tid >> 5, l = tid & 31;

    // ---- stable counting sort by expert (ballot ranking) ----
    if (tid < 8 * EN) ((int*)wcnt)[tid] = 0;
    __syncthreads();

    const int e = g_experts[tid];
    unsigned mk = __match_any_sync(0xffffffffu, e);
    int lower = __popc(mk & ((1u << l) - 1u));
    if (lower == 0) wcnt[w][e] = __popc(mk);
    __syncthreads();

    if (tid < EN) {
        int t = 0;
        #pragma unroll
        for (int ww = 0; ww < 8; ++ww) t += wcnt[ww][tid];
        s_offs[tid + 1] = t;
        if (t > 0) { s_ka[tid] = 0.5f; s_kb[tid] = 0.5f / (float)t; }
        else       { s_ka[tid] = 1.0f; s_kb[tid] = 0.0f; }
    }
    __syncthreads();
    if (tid == 0) {
        s_offs[0] = 0;
        #pragma unroll
        for (int i = 0; i < EN; ++i) s_offs[i + 1] += s_offs[i];
    }
    __syncthreads();

    {
        int rank = lower;
        #pragma unroll
        for (int ww = 0; ww < 8; ++ww)
            if (ww < w) rank += wcnt[ww][e];
        s_order[s_offs[e] + rank] = tid;
    }
    __syncthreads();

    // ---- streaming update ----
    const size_t j4 = (size_t)blockIdx.x * 256 + tid;
    const float4* x4 = (const float4*)x;
    const float4* m4 = (const float4*)mem;
    float4*       o4 = (float4*)outMem;

    #pragma unroll 1
    for (int ee = 0; ee < EN; ++ee) {
        float ax = 0.f, ay = 0.f, az = 0.f, aw = 0.f;
        const int lo = s_offs[ee];
        const int hi = s_offs[ee + 1];
        #pragma unroll 4
        for (int i = lo; i < hi; ++i) {
            int b = s_order[i];
            float4 f = x4[(size_t)b * K4N + j4];
            ax += f.x; ay += f.y; az += f.z; aw += f.w;
        }
        const float ka = s_ka[ee];
        const float kb = s_kb[ee];
        float4 mv = m4[(size_t)ee * K4N + j4];
        float4 ov;
        ov.x = ka * mv.x + kb * ax;
        ov.y = ka * mv.y + kb * ay;
        ov.z = ka * mv.z + kb * az;
        ov.w = ka * mv.w + kb * aw;
        o4[(size_t)ee * K4N + j4] = ov;
    }
}

// ---------------------------------------------------------------------------
extern "C" void kernel_launch(void* const* d_in, const int* in_sizes, int n_in,
                              void* d_out, int out_size)
{
    const float* x   = (const float*)d_in[0];
    const float* mem = (const float*)d_in[1];
    float* out = (float*)d_out;

    const long memElems = (long)EN * KN;          // 8388608
    float* outExp = nullptr;
    float* outMem = nullptr;
    if ((long)out_size == memElems + BN) {        // concat: experts then new_memory
        outExp = out;
        outMem = out + BN;
    } else if ((long)out_size == memElems) {      // new_memory only
        outMem = out;
    } else {                                      // experts only (fallback)
        outExp = out;
    }

    cudaFuncSetAttribute(k_dots, cudaFuncAttributeMaxDynamicSharedMemorySize, DSMEM);

    dim3 g1(NCH, 2);
    k_dots<<<g1, 256, DSMEM>>>(x, mem);
    k_argmax<<<BN, 256>>>(outExp);
    if (outMem) k_update<<<K4N / 256, 256>>>(x, mem, outMem);
}